// round 15
// baseline (speedup 1.0000x reference)
#include <cuda_runtime.h>
#include <math.h>

constexpr int T_ = 1024, H_ = 2048;
constexpr int HQ_ = 32, HKV_ = 4, D_ = 128;
constexpr int QKVN_ = HQ_*D_ + 2*HKV_*D_;   // 5120
constexpr int VOFF_ = HQ_*D_ + HKV_*D_;     // 4608
constexpr int E_ = 16, TOPK_ = 4, I_ = 768;
constexpr int TA_ = T_*TOPK_;               // 4096 assignments
constexpr int REP_ = HQ_/HKV_;              // 8

// ---------------- scratch (static device globals; no allocs allowed) -------
__device__ float g_x[T_*H_];
__device__ float g_res1[T_*H_];
__device__ float g_qkv[T_*QKVN_];
__device__ float g_q[T_*HQ_*D_];
__device__ float g_k[T_*HKV_*D_];
__device__ float g_attn[T_*HQ_*D_];
__device__ float g_attnproj[T_*H_];
__device__ float g_h2[T_*H_];
__device__ float g_x2[T_*H_];
__device__ float g_gu[(long long)TA_*2*I_];
__device__ float g_act[(long long)TA_*I_];
__device__ float g_dn[(long long)TA_*H_];
__device__ int   g_topk_idx[TA_];
__device__ float g_topk_w[TA_];
__device__ int   g_counts[E_];
__device__ int   g_offsets[E_+1];
__device__ int   g_assign_token[TA_];
__device__ float g_assign_w[TA_];
__device__ int   g_token_pos[TA_];
__device__ float g_cos[T_*64];
__device__ float g_sin[T_*64];

// ---------------- rope tables (split so tgemm is the 4th launch for ncu) ---
__global__ void rope_cos_kernel() {
    int idx = blockIdx.x*blockDim.x + threadIdx.x;
    if (idx >= T_*64) return;
    int i = idx & 63, t = idx >> 6;
    float invf = (float)exp(-(double)i/64.0 * 13.815510557964274); // ln(1e6)
    float f = (float)t * invf;
    float s, c;
    sincosf(f, &s, &c);
    g_cos[idx] = c;
}
__global__ void rope_sin_kernel() {
    int idx = blockIdx.x*blockDim.x + threadIdx.x;
    if (idx >= T_*64) return;
    int i = idx & 63, t = idx >> 6;
    float invf = (float)exp(-(double)i/64.0 * 13.815510557964274);
    float f = (float)t * invf;
    float s, c;
    sincosf(f, &s, &c);
    g_sin[idx] = s;
}

// ---------------- fused add + rmsnorm --------------------------------------
__global__ void add_norm_kernel(const float* __restrict__ a, const float* __restrict__ b,
                                const float* __restrict__ w,
                                float* __restrict__ xo, float* __restrict__ ro) {
    int t = blockIdx.x, tid = threadIdx.x;
    float vals[8]; float ss = 0.f;
    #pragma unroll
    for (int j = 0; j < 8; j++) {
        int i = tid + j*256;
        float v = a[(long long)t*H_ + i] + b[(long long)t*H_ + i];
        vals[j] = v; ss += v*v;
    }
    #pragma unroll
    for (int off = 16; off; off >>= 1) ss += __shfl_xor_sync(~0u, ss, off);
    __shared__ float sred[8];
    if ((tid & 31) == 0) sred[tid >> 5] = ss;
    __syncthreads();
    float tot = 0.f;
    #pragma unroll
    for (int k = 0; k < 8; k++) tot += sred[k];
    float r = rsqrtf(tot/(float)H_ + 1e-6f);
    #pragma unroll
    for (int j = 0; j < 8; j++) {
        int i = tid + j*256;
        ro[(long long)t*H_ + i] = vals[j];
        xo[(long long)t*H_ + i] = vals[j]*r*w[i];
    }
}

// ---------------- tf32 tensor-core GEMM, 4-stage cp.async pipeline ---------
// C[row] = A[arow] @ B(+e*strideB); optional gather + row scale (MoE).
// 128x64 block tile, 8 warps, warp tile 32x32 (2x4 m16n8k8 tf32 mma).
// smem holds raw fp32 (cp.async path); cvt.rna on the fragment-load path —
// bitwise-identical products to the R10 passing kernel.
__device__ __forceinline__ unsigned tf32u(float f) {
    unsigned u;
    asm("cvt.rna.tf32.f32 %0, %1;" : "=r"(u) : "f"(f));
    return u;
}
__device__ __forceinline__ void cp_async16(void* smem, const void* gmem) {
    unsigned saddr = (unsigned)__cvta_generic_to_shared(smem);
    asm volatile("cp.async.cg.shared.global [%0], [%1], 16;" :: "r"(saddr), "l"(gmem));
}
__device__ __forceinline__ void mma_tf32(float& d0, float& d1, float& d2, float& d3,
                                         unsigned a0, unsigned a1, unsigned a2, unsigned a3,
                                         unsigned b0, unsigned b1) {
    asm volatile("mma.sync.aligned.m16n8k8.row.col.f32.tf32.tf32.f32 "
                 "{%0,%1,%2,%3},{%4,%5,%6,%7},{%8,%9},{%0,%1,%2,%3};"
                 : "+f"(d0), "+f"(d1), "+f"(d2), "+f"(d3)
                 : "r"(a0), "r"(a1), "r"(a2), "r"(a3), "r"(b0), "r"(b1));
}

__global__ void tgemm(const float* __restrict__ A, const float* __restrict__ B,
                      float* __restrict__ C, int M, int N, int K,
                      int lda, int ldb, int ldc,
                      const int* __restrict__ counts, const int* __restrict__ offsets,
                      const int* __restrict__ gatherA, const float* __restrict__ rowScale,
                      long long strideB) {
    __shared__ float As[4][128][20];   // stride 20: conflict-free frag loads
    __shared__ float Bs[4][16][72];    // stride 72: conflict-free frag loads
    int tid = threadIdx.x;
    int e = blockIdx.z;
    int cnt = M, base = 0;
    const float* Bp = B;
    if (counts) {
        cnt = counts[e]; base = offsets[e];
        if (cnt == 0) return;
        Bp = B + (long long)e * strideB;
    }
    int m0 = blockIdx.y * 128;
    if (m0 >= cnt) return;
    int n0 = blockIdx.x * 64;

    // A loader: one row per thread, 8 contiguous cols (2x 16B cp.async)
    int ar = tid >> 1, ac = (tid & 1) * 8;
    int grow = base + m0 + ar;
    int clampg = min(grow, base + cnt - 1);
    int arow = gatherA ? gatherA[clampg] : clampg;
    const float* Aptr = A + (long long)arow * lda;
    // B loader: 16 rows x 64 cols, 4 cols per thread (1x 16B cp.async)
    int br = tid >> 4, bc = (tid & 15) * 4;

    int wid = tid >> 5, lane = tid & 31, gid = lane >> 2, tig = lane & 3;
    int wm = (wid & 3) * 32, wn = (wid >> 2) * 32;

    float acc[2][4][4];
    #pragma unroll
    for (int mt = 0; mt < 2; mt++)
        #pragma unroll
        for (int nt = 0; nt < 4; nt++)
            #pragma unroll
            for (int i = 0; i < 4; i++) acc[mt][nt][i] = 0.f;

    int nk = K >> 4;   // k16 tiles; all K here are multiples of 16, nk >= 48

    // prologue: issue stages for k-tiles 0..2
    #pragma unroll
    for (int s = 0; s < 3; s++) {
        const float* a_src = Aptr + s*16 + ac;
        cp_async16(&As[s][ar][ac],     a_src);
        cp_async16(&As[s][ar][ac + 4], a_src + 4);
        cp_async16(&Bs[s][br][bc], Bp + (long long)(s*16 + br)*ldb + n0 + bc);
        asm volatile("cp.async.commit_group;");
    }

    for (int kt = 0; kt < nk; kt++) {
        // complete group kt (pending is always exactly 3 committed-not-waited)
        asm volatile("cp.async.wait_group 2;");
        __syncthreads();

        // issue k-tile kt+3 into stage (kt+3)&3 == (kt-1)&3, whose readers
        // all finished before the barrier above. Empty commit keeps the
        // wait_group accounting exact in the tail.
        int ktn = kt + 3;
        if (ktn < nk) {
            int sn = ktn & 3;
            const float* a_src = Aptr + ktn*16 + ac;
            cp_async16(&As[sn][ar][ac],     a_src);
            cp_async16(&As[sn][ar][ac + 4], a_src + 4);
            cp_async16(&Bs[sn][br][bc], Bp + (long long)(ktn*16 + br)*ldb + n0 + bc);
        }
        asm volatile("cp.async.commit_group;");

        int st = kt & 3;
        #pragma unroll
        for (int ks = 0; ks < 16; ks += 8) {
            unsigned af[2][4], bf[4][2];
            #pragma unroll
            for (int mt = 0; mt < 2; mt++) {
                int r = wm + mt*16 + gid;
                af[mt][0] = tf32u(As[st][r    ][ks + tig]);
                af[mt][1] = tf32u(As[st][r + 8][ks + tig]);
                af[mt][2] = tf32u(As[st][r    ][ks + tig + 4]);
                af[mt][3] = tf32u(As[st][r + 8][ks + tig + 4]);
            }
            #pragma unroll
            for (int nt = 0; nt < 4; nt++) {
                int c = wn + nt*8 + gid;
                bf[nt][0] = tf32u(Bs[st][ks + tig    ][c]);
                bf[nt][1] = tf32u(Bs[st][ks + tig + 4][c]);
            }
            #pragma unroll
            for (int mt = 0; mt < 2; mt++)
                #pragma unroll
                for (int nt = 0; nt < 4; nt++)
                    mma_tf32(acc[mt][nt][0], acc[mt][nt][1], acc[mt][nt][2], acc[mt][nt][3],
                             af[mt][0], af[mt][1], af[mt][2], af[mt][3],
                             bf[nt][0], bf[nt][1]);
        }
    }

    // epilogue
    #pragma unroll
    for (int mt = 0; mt < 2; mt++) {
        int mrow0 = m0 + wm + mt*16 + gid;
        #pragma unroll
        for (int half = 0; half < 2; half++) {
            int m = mrow0 + half*8;
            if (m < cnt) {
                int gr = base + m;
                float sc = rowScale ? rowScale[gr] : 1.f;
                #pragma unroll
                for (int nt = 0; nt < 4; nt++) {
                    int col = n0 + wn + nt*8 + 2*tig;
                    float2 v = make_float2(acc[mt][nt][half*2 + 0]*sc,
                                           acc[mt][nt][half*2 + 1]*sc);
                    *reinterpret_cast<float2*>(&C[(long long)gr*ldc + col]) = v;
                }
            }
        }
    }
}

// ---------------- per-head q/k rmsnorm + rope ------------------------------
__global__ void qknorm_rope_kernel(const float* __restrict__ qnw,
                                   const float* __restrict__ knw) {
    int t = blockIdx.x, hh = blockIdx.y, tid = threadIdx.x;
    bool isq = hh < HQ_;
    const float* src = g_qkv + (long long)t*QKVN_ + (isq ? hh*D_ : HQ_*D_ + (hh-HQ_)*D_);
    float v = src[tid];
    float ss = v*v;
    #pragma unroll
    for (int off = 16; off; off >>= 1) ss += __shfl_xor_sync(~0u, ss, off);
    __shared__ float sred[4];
    if ((tid & 31) == 0) sred[tid >> 5] = ss;
    __syncthreads();
    float tot = sred[0] + sred[1] + sred[2] + sred[3];
    float r = rsqrtf(tot/128.f + 1e-6f);
    float w = isq ? qnw[tid] : knw[tid];
    __shared__ float sb[128];
    sb[tid] = v*r*w;
    __syncthreads();
    int i = tid & 63;
    float c = g_cos[t*64 + i], s = g_sin[t*64 + i];
    float out = (tid < 64) ? sb[tid]*c - sb[tid+64]*s
                           : sb[tid]*c + sb[tid-64]*s;
    if (isq) g_q[((long long)t*HQ_ + hh)*D_ + tid] = out;
    else     g_k[((long long)t*HKV_ + (hh-HQ_))*D_ + tid] = out;
}

// ---------------- causal GQA attention (warp-per-query, shared K/V tiles) --
__global__ void attn_kernel() {
    __shared__ float Ks[32][128];
    __shared__ float Vs[32][128];
    int qb = blockIdx.x, h = blockIdx.y;
    int tid = threadIdx.x, wid = tid >> 5, lane = tid & 31;
    int t = qb*8 + wid;
    int kvh = h / REP_;
    const float scale = 0.08838834764831845f;  // 1/sqrt(128)
    float4 qv = *reinterpret_cast<const float4*>(&g_q[((long long)t*HQ_ + h)*D_ + lane*4]);
    float q0 = qv.x*scale, q1 = qv.y*scale, q2 = qv.z*scale, q3 = qv.w*scale;
    float m = -INFINITY, l = 0.f, o0 = 0.f, o1 = 0.f, o2 = 0.f, o3 = 0.f;
    int tmax = qb*8 + 7;
    for (int s0 = 0; s0 <= tmax; s0 += 32) {
        __syncthreads();
        #pragma unroll
        for (int it = 0; it < 4; it++) {
            int lin = tid + it*256;
            int row = lin >> 5, c4 = (lin & 31)*4;
            *reinterpret_cast<float4*>(&Ks[row][c4]) =
                *reinterpret_cast<const float4*>(&g_k[((long long)(s0+row)*HKV_ + kvh)*D_ + c4]);
            *reinterpret_cast<float4*>(&Vs[row][c4]) =
                *reinterpret_cast<const float4*>(&g_qkv[(long long)(s0+row)*QKVN_ + VOFF_ + kvh*D_ + c4]);
        }
        __syncthreads();
        int lim = min(31, t - s0);
        for (int s = 0; s <= lim; s++) {
            float4 k4 = *reinterpret_cast<const float4*>(&Ks[s][lane*4]);
            float d = q0*k4.x + q1*k4.y + q2*k4.z + q3*k4.w;
            #pragma unroll
            for (int off = 16; off; off >>= 1) d += __shfl_xor_sync(~0u, d, off);
            float mnew = fmaxf(m, d);
            float c = __expf(m - mnew);
            float p = __expf(d - mnew);
            l = l*c + p;
            float4 v4 = *reinterpret_cast<const float4*>(&Vs[s][lane*4]);
            o0 = o0*c + p*v4.x; o1 = o1*c + p*v4.y;
            o2 = o2*c + p*v4.z; o3 = o3*c + p*v4.w;
            m = mnew;
        }
    }
    float inv = 1.f/l;
    float4 out = make_float4(o0*inv, o1*inv, o2*inv, o3*inv);
    *reinterpret_cast<float4*>(&g_attn[((long long)t*HQ_ + h)*D_ + lane*4]) = out;
}

// ---------------- router: logits + softmax + top-4 (normalized) ------------
__global__ void router_kernel(const float* __restrict__ gate_w) {
    int t = blockIdx.x, tid = threadIdx.x;
    int wid = tid >> 5, lane = tid & 31;
    __shared__ float slog[E_];
    if (wid < E_) {
        const float* xr = g_x2 + (long long)t*H_;
        float acc = 0.f;
        for (int hh = lane; hh < H_; hh += 32)
            acc += xr[hh]*gate_w[hh*E_ + wid];
        #pragma unroll
        for (int off = 16; off; off >>= 1) acc += __shfl_xor_sync(~0u, acc, off);
        if (lane == 0) slog[wid] = acc;
    }
    __syncthreads();
    if (tid == 0) {
        float mx = -INFINITY;
        for (int e = 0; e < E_; e++) mx = fmaxf(mx, slog[e]);
        float p[E_]; float sum = 0.f;
        for (int e = 0; e < E_; e++) { p[e] = expf(slog[e]-mx); sum += p[e]; }
        float inv = 1.f/sum;
        for (int e = 0; e < E_; e++) p[e] *= inv;
        float wsum = 0.f; int idxs[TOPK_]; float vals[TOPK_];
        for (int k = 0; k < TOPK_; k++) {
            int bi = 0; float bv = -1.f;
            for (int e = 0; e < E_; e++) if (p[e] > bv) { bv = p[e]; bi = e; }
            idxs[k] = bi; vals[k] = bv; p[bi] = -2.f; wsum += bv;
        }
        float invw = 1.f/wsum;
        for (int k = 0; k < TOPK_; k++) {
            g_topk_idx[t*TOPK_ + k] = idxs[k];
            g_topk_w[t*TOPK_ + k]   = vals[k]*invw;
        }
    }
}

// ---------------- group assignments by expert ------------------------------
__global__ void assign_kernel() {
    __shared__ int scnt[E_], soff[E_+1], scur[E_];
    int tid = threadIdx.x;
    if (tid < E_) scnt[tid] = 0;
    __syncthreads();
    for (int r = tid; r < TA_; r += 256) atomicAdd(&scnt[g_topk_idx[r]], 1);
    __syncthreads();
    if (tid == 0) {
        soff[0] = 0;
        for (int e = 0; e < E_; e++) soff[e+1] = soff[e] + scnt[e];
    }
    __syncthreads();
    if (tid < E_) {
        scur[tid] = soff[tid];
        g_counts[tid] = scnt[tid];
        g_offsets[tid] = soff[tid];
    }
    if (tid == 0) g_offsets[E_] = TA_;
    __syncthreads();
    for (int r = tid; r < TA_; r += 256) {
        int e = g_topk_idx[r];
        int pos = atomicAdd(&scur[e], 1);
        g_assign_token[pos] = r >> 2;
        g_assign_w[pos]     = g_topk_w[r];
        g_token_pos[r]      = pos;
    }
}

// ---------------- silu(gate)*up --------------------------------------------
__global__ void act_kernel() {
    long long idx = (long long)blockIdx.x*blockDim.x + threadIdx.x;
    if (idx >= (long long)TA_*I_) return;
    int r = (int)(idx / I_), i = (int)(idx % I_);
    float g = g_gu[(long long)r*(2*I_) + i];
    float u = g_gu[(long long)r*(2*I_) + I_ + i];
    g_act[idx] = g/(1.f + __expf(-g))*u;
}

// ---------------- combine 4 expert outputs per token + residual out --------
__global__ void combine_kernel(float* __restrict__ out, int writeRes) {
    int t = blockIdx.x, tid = threadIdx.x;
    int p0 = g_token_pos[t*4+0], p1 = g_token_pos[t*4+1];
    int p2 = g_token_pos[t*4+2], p3 = g_token_pos[t*4+3];
    for (int hh = tid; hh < H_; hh += 256) {
        float v = g_dn[(long long)p0*H_+hh] + g_dn[(long long)p1*H_+hh]
                + g_dn[(long long)p2*H_+hh] + g_dn[(long long)p3*H_+hh];
        out[(long long)t*H_ + hh] = v;
        if (writeRes)
            out[(long long)T_*H_ + (long long)t*H_ + hh] = g_h2[(long long)t*H_ + hh];
    }
}

// ---------------------------------------------------------------------------
extern "C" void kernel_launch(void* const* d_in, const int* in_sizes, int n_in,
                              void* d_out, int out_size) {
    const float* hidden   = (const float*)d_in[1];
    const float* residual = (const float*)d_in[2];
    const float* w_qkv    = (const float*)d_in[3];
    const float* w_o      = (const float*)d_in[4];
    const float* qnw      = (const float*)d_in[5];
    const float* knw      = (const float*)d_in[6];
    const float* inw      = (const float*)d_in[7];
    const float* postw    = (const float*)d_in[8];
    const float* gate_w   = (const float*)d_in[9];
    const float* Wgu      = (const float*)d_in[10];
    const float* Wdn      = (const float*)d_in[11];
    float* out = (float*)d_out;

    float *px, *pres1, *pqkv, *pattn, *pattnproj, *ph2, *px2, *pgu, *pact, *pdn, *passw;
    int *pcnt, *poff, *ptok;
    cudaGetSymbolAddress((void**)&px,        g_x);
    cudaGetSymbolAddress((void**)&pres1,     g_res1);
    cudaGetSymbolAddress((void**)&pqkv,      g_qkv);
    cudaGetSymbolAddress((void**)&pattn,     g_attn);
    cudaGetSymbolAddress((void**)&pattnproj, g_attnproj);
    cudaGetSymbolAddress((void**)&ph2,       g_h2);
    cudaGetSymbolAddress((void**)&px2,       g_x2);
    cudaGetSymbolAddress((void**)&pgu,       g_gu);
    cudaGetSymbolAddress((void**)&pact,      g_act);
    cudaGetSymbolAddress((void**)&pdn,       g_dn);
    cudaGetSymbolAddress((void**)&passw,     g_assign_w);
    cudaGetSymbolAddress((void**)&pcnt,      g_counts);
    cudaGetSymbolAddress((void**)&poff,      g_offsets);
    cudaGetSymbolAddress((void**)&ptok,      g_assign_token);

    // launch order arranged so tgemm(QKV) is launch #4 (the ncu capture slot)
    // h = hidden + residual; res1 = h; x = rmsnorm(h)
    add_norm_kernel<<<T_, 256>>>(hidden, residual, inw, px, pres1);
    rope_cos_kernel<<<(T_*64 + 255)/256, 256>>>();
    rope_sin_kernel<<<(T_*64 + 255)/256, 256>>>();
    // qkv = x @ w_qkv   [1024 x 5120], K=2048
    tgemm<<<dim3(QKVN_/64, T_/128, 1), 256>>>(px, w_qkv, pqkv, T_, QKVN_, H_,
                                              H_, QKVN_, QKVN_,
                                              nullptr, nullptr, nullptr, nullptr, 0);
    // per-head norm + rope
    qknorm_rope_kernel<<<dim3(T_, HQ_+HKV_), 128>>>(qnw, knw);
    // causal GQA attention
    attn_kernel<<<dim3(T_/8, HQ_), 256>>>();
    // attn_out = o @ w_o   [1024 x 2048], K=4096
    tgemm<<<dim3(H_/64, T_/128, 1), 256>>>(pattn, w_o, pattnproj, T_, H_, HQ_*D_,
                                           HQ_*D_, H_, H_,
                                           nullptr, nullptr, nullptr, nullptr, 0);
    // h2 = attn_out + res1; x2 = rmsnorm(h2)
    add_norm_kernel<<<T_, 256>>>(pattnproj, pres1, postw, px2, ph2);
    // router + top-4
    router_kernel<<<T_, 512>>>(gate_w);
    assign_kernel<<<1, 256>>>();
    // per-expert gu = gather(x2) @ W_gu[e]   [cnt x 1536], K=2048
    tgemm<<<dim3(2*I_/64, TA_/128, E_), 256>>>(px2, Wgu, pgu, TA_, 2*I_, H_,
                                               H_, 2*I_, 2*I_,
                                               pcnt, poff, ptok, nullptr,
                                               (long long)H_*2*I_);
    // act = silu(gate)*up
    act_kernel<<<(int)(((long long)TA_*I_ + 255)/256), 256>>>();
    // per-expert down = act @ W_down[e] * routing_w  [cnt x 2048], K=768
    tgemm<<<dim3(H_/64, TA_/128, E_), 256>>>(pact, Wdn, pdn, TA_, H_, I_,
                                             I_, H_, H_,
                                             pcnt, poff, nullptr, passw,
                                             (long long)I_*H_);
    // moe_out + residual out
    combine_kernel<<<T_, 256>>>(out, (out_size >= 2*T_*H_) ? 1 : 0);
}

// round 16
// speedup vs baseline: 1.0162x; 1.0162x over previous
#include <cuda_runtime.h>
#include <math.h>

constexpr int T_ = 1024, H_ = 2048;
constexpr int HQ_ = 32, HKV_ = 4, D_ = 128;
constexpr int QKVN_ = HQ_*D_ + 2*HKV_*D_;   // 5120
constexpr int VOFF_ = HQ_*D_ + HKV_*D_;     // 4608
constexpr int E_ = 16, TOPK_ = 4, I_ = 768;
constexpr int TA_ = T_*TOPK_;               // 4096 assignments
constexpr int REP_ = HQ_/HKV_;              // 8

// ---------------- scratch (static device globals; no allocs allowed) -------
__device__ float g_x[T_*H_];
__device__ float g_res1[T_*H_];
__device__ float g_qkv[T_*QKVN_];
__device__ float g_q[T_*HQ_*D_];
__device__ float g_k[T_*HKV_*D_];
__device__ float g_attn[T_*HQ_*D_];
__device__ float g_attnproj[T_*H_];
__device__ float g_h2[T_*H_];
__device__ float g_x2[T_*H_];
__device__ float g_gu[(long long)TA_*2*I_];
__device__ float g_act[(long long)TA_*I_];
__device__ float g_dn[(long long)TA_*H_];
__device__ int   g_topk_idx[TA_];
__device__ float g_topk_w[TA_];
__device__ int   g_counts[E_];
__device__ int   g_offsets[E_+1];
__device__ int   g_assign_token[TA_];
__device__ float g_assign_w[TA_];
__device__ int   g_token_pos[TA_];
__device__ float g_cos[T_*64];
__device__ float g_sin[T_*64];

// ---------------- rope tables (split so tgemm is the 4th launch for ncu) ---
__global__ void rope_cos_kernel() {
    int idx = blockIdx.x*blockDim.x + threadIdx.x;
    if (idx >= T_*64) return;
    int i = idx & 63, t = idx >> 6;
    float invf = (float)exp(-(double)i/64.0 * 13.815510557964274); // ln(1e6)
    float f = (float)t * invf;
    float s, c;
    sincosf(f, &s, &c);
    g_cos[idx] = c;
}
__global__ void rope_sin_kernel() {
    int idx = blockIdx.x*blockDim.x + threadIdx.x;
    if (idx >= T_*64) return;
    int i = idx & 63, t = idx >> 6;
    float invf = (float)exp(-(double)i/64.0 * 13.815510557964274);
    float f = (float)t * invf;
    float s, c;
    sincosf(f, &s, &c);
    g_sin[idx] = s;
}

// ---------------- fused add + rmsnorm --------------------------------------
__global__ void add_norm_kernel(const float* __restrict__ a, const float* __restrict__ b,
                                const float* __restrict__ w,
                                float* __restrict__ xo, float* __restrict__ ro) {
    int t = blockIdx.x, tid = threadIdx.x;
    float vals[8]; float ss = 0.f;
    #pragma unroll
    for (int j = 0; j < 8; j++) {
        int i = tid + j*256;
        float v = a[(long long)t*H_ + i] + b[(long long)t*H_ + i];
        vals[j] = v; ss += v*v;
    }
    #pragma unroll
    for (int off = 16; off; off >>= 1) ss += __shfl_xor_sync(~0u, ss, off);
    __shared__ float sred[8];
    if ((tid & 31) == 0) sred[tid >> 5] = ss;
    __syncthreads();
    float tot = 0.f;
    #pragma unroll
    for (int k = 0; k < 8; k++) tot += sred[k];
    float r = rsqrtf(tot/(float)H_ + 1e-6f);
    #pragma unroll
    for (int j = 0; j < 8; j++) {
        int i = tid + j*256;
        ro[(long long)t*H_ + i] = vals[j];
        xo[(long long)t*H_ + i] = vals[j]*r*w[i];
    }
}

// ---------------- tf32 tensor-core GEMM, 3-stage cp.async, 4 CTAs/SM -------
// C[row] = A[arow] @ B(+e*strideB); optional gather + row scale (MoE).
// 128x64 block tile, 8 warps, warp tile 32x32 (2x4 m16n8k8 tf32 mma).
// Occupancy-first: 3 stages (44.5KB smem) + launch_bounds(256,4) -> 4 CTAs/SM
// to hide LDS->mma latency chains (R15 profile: occ 30.7%, issue 39.7%).
// k-chunk order unchanged -> C bitwise identical to R10/R15 (rel_err oracle).
__device__ __forceinline__ unsigned tf32u(float f) {
    unsigned u;
    asm("cvt.rna.tf32.f32 %0, %1;" : "=r"(u) : "f"(f));
    return u;
}
__device__ __forceinline__ void cp_async16(void* smem, const void* gmem) {
    unsigned saddr = (unsigned)__cvta_generic_to_shared(smem);
    asm volatile("cp.async.cg.shared.global [%0], [%1], 16;" :: "r"(saddr), "l"(gmem));
}
__device__ __forceinline__ void mma_tf32(float& d0, float& d1, float& d2, float& d3,
                                         unsigned a0, unsigned a1, unsigned a2, unsigned a3,
                                         unsigned b0, unsigned b1) {
    asm volatile("mma.sync.aligned.m16n8k8.row.col.f32.tf32.tf32.f32 "
                 "{%0,%1,%2,%3},{%4,%5,%6,%7},{%8,%9},{%0,%1,%2,%3};"
                 : "+f"(d0), "+f"(d1), "+f"(d2), "+f"(d3)
                 : "r"(a0), "r"(a1), "r"(a2), "r"(a3), "r"(b0), "r"(b1));
}

__global__ void __launch_bounds__(256, 4)
tgemm(const float* __restrict__ A, const float* __restrict__ B,
      float* __restrict__ C, int M, int N, int K,
      int lda, int ldb, int ldc,
      const int* __restrict__ counts, const int* __restrict__ offsets,
      const int* __restrict__ gatherA, const float* __restrict__ rowScale,
      long long strideB) {
    __shared__ float As[3][128][20];   // stride 20: conflict-free frag loads
    __shared__ float Bs[3][16][72];    // stride 72: conflict-free frag loads
    int tid = threadIdx.x;
    int e = blockIdx.z;
    int cnt = M, base = 0;
    const float* Bp = B;
    if (counts) {
        cnt = counts[e]; base = offsets[e];
        if (cnt == 0) return;
        Bp = B + (long long)e * strideB;
    }
    int m0 = blockIdx.y * 128;
    if (m0 >= cnt) return;
    int n0 = blockIdx.x * 64;

    // A loader: one row per thread, 8 contiguous cols (2x 16B cp.async)
    int ar = tid >> 1, ac = (tid & 1) * 8;
    int grow = base + m0 + ar;
    int clampg = min(grow, base + cnt - 1);
    int arow = gatherA ? gatherA[clampg] : clampg;
    const float* Aptr = A + (long long)arow * lda;
    // B loader: 16 rows x 64 cols, 4 cols per thread (1x 16B cp.async)
    int br = tid >> 4, bc = (tid & 15) * 4;

    int wid = tid >> 5, lane = tid & 31, gid = lane >> 2, tig = lane & 3;
    int wm = (wid & 3) * 32, wn = (wid >> 2) * 32;

    float acc[2][4][4];
    #pragma unroll
    for (int mt = 0; mt < 2; mt++)
        #pragma unroll
        for (int nt = 0; nt < 4; nt++)
            #pragma unroll
            for (int i = 0; i < 4; i++) acc[mt][nt][i] = 0.f;

    int nk = K >> 4;   // k16 tiles; all K here are multiples of 16, nk >= 48

    // prologue: issue stages for k-tiles 0..1
    #pragma unroll
    for (int s = 0; s < 2; s++) {
        const float* a_src = Aptr + s*16 + ac;
        cp_async16(&As[s][ar][ac],     a_src);
        cp_async16(&As[s][ar][ac + 4], a_src + 4);
        cp_async16(&Bs[s][br][bc], Bp + (long long)(s*16 + br)*ldb + n0 + bc);
        asm volatile("cp.async.commit_group;");
    }

    int st = 0;
    for (int kt = 0; kt < nk; kt++) {
        // complete group kt (pending is always exactly 2 committed-not-waited)
        asm volatile("cp.async.wait_group 1;");
        __syncthreads();

        // issue k-tile kt+2 into stage (kt+2)%3 == (kt-1)%3, whose readers
        // all finished before the barrier above. Empty commit keeps the
        // wait_group accounting exact in the tail.
        int ktn = kt + 2;
        if (ktn < nk) {
            int sn = st + 2; if (sn >= 3) sn -= 3;
            const float* a_src = Aptr + ktn*16 + ac;
            cp_async16(&As[sn][ar][ac],     a_src);
            cp_async16(&As[sn][ar][ac + 4], a_src + 4);
            cp_async16(&Bs[sn][br][bc], Bp + (long long)(ktn*16 + br)*ldb + n0 + bc);
        }
        asm volatile("cp.async.commit_group;");

        #pragma unroll
        for (int ks = 0; ks < 16; ks += 8) {
            unsigned af[2][4], bf[4][2];
            #pragma unroll
            for (int mt = 0; mt < 2; mt++) {
                int r = wm + mt*16 + gid;
                af[mt][0] = tf32u(As[st][r    ][ks + tig]);
                af[mt][1] = tf32u(As[st][r + 8][ks + tig]);
                af[mt][2] = tf32u(As[st][r    ][ks + tig + 4]);
                af[mt][3] = tf32u(As[st][r + 8][ks + tig + 4]);
            }
            #pragma unroll
            for (int nt = 0; nt < 4; nt++) {
                int c = wn + nt*8 + gid;
                bf[nt][0] = tf32u(Bs[st][ks + tig    ][c]);
                bf[nt][1] = tf32u(Bs[st][ks + tig + 4][c]);
            }
            #pragma unroll
            for (int mt = 0; mt < 2; mt++)
                #pragma unroll
                for (int nt = 0; nt < 4; nt++)
                    mma_tf32(acc[mt][nt][0], acc[mt][nt][1], acc[mt][nt][2], acc[mt][nt][3],
                             af[mt][0], af[mt][1], af[mt][2], af[mt][3],
                             bf[nt][0], bf[nt][1]);
        }
        st++; if (st >= 3) st = 0;
    }

    // epilogue
    #pragma unroll
    for (int mt = 0; mt < 2; mt++) {
        int mrow0 = m0 + wm + mt*16 + gid;
        #pragma unroll
        for (int half = 0; half < 2; half++) {
            int m = mrow0 + half*8;
            if (m < cnt) {
                int gr = base + m;
                float sc = rowScale ? rowScale[gr] : 1.f;
                #pragma unroll
                for (int nt = 0; nt < 4; nt++) {
                    int col = n0 + wn + nt*8 + 2*tig;
                    float2 v = make_float2(acc[mt][nt][half*2 + 0]*sc,
                                           acc[mt][nt][half*2 + 1]*sc);
                    *reinterpret_cast<float2*>(&C[(long long)gr*ldc + col]) = v;
                }
            }
        }
    }
}

// ---------------- per-head q/k rmsnorm + rope ------------------------------
__global__ void qknorm_rope_kernel(const float* __restrict__ qnw,
                                   const float* __restrict__ knw) {
    int t = blockIdx.x, hh = blockIdx.y, tid = threadIdx.x;
    bool isq = hh < HQ_;
    const float* src = g_qkv + (long long)t*QKVN_ + (isq ? hh*D_ : HQ_*D_ + (hh-HQ_)*D_);
    float v = src[tid];
    float ss = v*v;
    #pragma unroll
    for (int off = 16; off; off >>= 1) ss += __shfl_xor_sync(~0u, ss, off);
    __shared__ float sred[4];
    if ((tid & 31) == 0) sred[tid >> 5] = ss;
    __syncthreads();
    float tot = sred[0] + sred[1] + sred[2] + sred[3];
    float r = rsqrtf(tot/128.f + 1e-6f);
    float w = isq ? qnw[tid] : knw[tid];
    __shared__ float sb[128];
    sb[tid] = v*r*w;
    __syncthreads();
    int i = tid & 63;
    float c = g_cos[t*64 + i], s = g_sin[t*64 + i];
    float out = (tid < 64) ? sb[tid]*c - sb[tid+64]*s
                           : sb[tid]*c + sb[tid-64]*s;
    if (isq) g_q[((long long)t*HQ_ + hh)*D_ + tid] = out;
    else     g_k[((long long)t*HKV_ + (hh-HQ_))*D_ + tid] = out;
}

// ---------------- causal GQA attention (warp-per-query, shared K/V tiles) --
__global__ void attn_kernel() {
    __shared__ float Ks[32][128];
    __shared__ float Vs[32][128];
    int qb = blockIdx.x, h = blockIdx.y;
    int tid = threadIdx.x, wid = tid >> 5, lane = tid & 31;
    int t = qb*8 + wid;
    int kvh = h / REP_;
    const float scale = 0.08838834764831845f;  // 1/sqrt(128)
    float4 qv = *reinterpret_cast<const float4*>(&g_q[((long long)t*HQ_ + h)*D_ + lane*4]);
    float q0 = qv.x*scale, q1 = qv.y*scale, q2 = qv.z*scale, q3 = qv.w*scale;
    float m = -INFINITY, l = 0.f, o0 = 0.f, o1 = 0.f, o2 = 0.f, o3 = 0.f;
    int tmax = qb*8 + 7;
    for (int s0 = 0; s0 <= tmax; s0 += 32) {
        __syncthreads();
        #pragma unroll
        for (int it = 0; it < 4; it++) {
            int lin = tid + it*256;
            int row = lin >> 5, c4 = (lin & 31)*4;
            *reinterpret_cast<float4*>(&Ks[row][c4]) =
                *reinterpret_cast<const float4*>(&g_k[((long long)(s0+row)*HKV_ + kvh)*D_ + c4]);
            *reinterpret_cast<float4*>(&Vs[row][c4]) =
                *reinterpret_cast<const float4*>(&g_qkv[(long long)(s0+row)*QKVN_ + VOFF_ + kvh*D_ + c4]);
        }
        __syncthreads();
        int lim = min(31, t - s0);
        for (int s = 0; s <= lim; s++) {
            float4 k4 = *reinterpret_cast<const float4*>(&Ks[s][lane*4]);
            float d = q0*k4.x + q1*k4.y + q2*k4.z + q3*k4.w;
            #pragma unroll
            for (int off = 16; off; off >>= 1) d += __shfl_xor_sync(~0u, d, off);
            float mnew = fmaxf(m, d);
            float c = __expf(m - mnew);
            float p = __expf(d - mnew);
            l = l*c + p;
            float4 v4 = *reinterpret_cast<const float4*>(&Vs[s][lane*4]);
            o0 = o0*c + p*v4.x; o1 = o1*c + p*v4.y;
            o2 = o2*c + p*v4.z; o3 = o3*c + p*v4.w;
            m = mnew;
        }
    }
    float inv = 1.f/l;
    float4 out = make_float4(o0*inv, o1*inv, o2*inv, o3*inv);
    *reinterpret_cast<float4*>(&g_attn[((long long)t*HQ_ + h)*D_ + lane*4]) = out;
}

// ---------------- router: logits + softmax + top-4 (normalized) ------------
__global__ void router_kernel(const float* __restrict__ gate_w) {
    int t = blockIdx.x, tid = threadIdx.x;
    int wid = tid >> 5, lane = tid & 31;
    __shared__ float slog[E_];
    if (wid < E_) {
        const float* xr = g_x2 + (long long)t*H_;
        float acc = 0.f;
        for (int hh = lane; hh < H_; hh += 32)
            acc += xr[hh]*gate_w[hh*E_ + wid];
        #pragma unroll
        for (int off = 16; off; off >>= 1) acc += __shfl_xor_sync(~0u, acc, off);
        if (lane == 0) slog[wid] = acc;
    }
    __syncthreads();
    if (tid == 0) {
        float mx = -INFINITY;
        for (int e = 0; e < E_; e++) mx = fmaxf(mx, slog[e]);
        float p[E_]; float sum = 0.f;
        for (int e = 0; e < E_; e++) { p[e] = expf(slog[e]-mx); sum += p[e]; }
        float inv = 1.f/sum;
        for (int e = 0; e < E_; e++) p[e] *= inv;
        float wsum = 0.f; int idxs[TOPK_]; float vals[TOPK_];
        for (int k = 0; k < TOPK_; k++) {
            int bi = 0; float bv = -1.f;
            for (int e = 0; e < E_; e++) if (p[e] > bv) { bv = p[e]; bi = e; }
            idxs[k] = bi; vals[k] = bv; p[bi] = -2.f; wsum += bv;
        }
        float invw = 1.f/wsum;
        for (int k = 0; k < TOPK_; k++) {
            g_topk_idx[t*TOPK_ + k] = idxs[k];
            g_topk_w[t*TOPK_ + k]   = vals[k]*invw;
        }
    }
}

// ---------------- group assignments by expert ------------------------------
__global__ void assign_kernel() {
    __shared__ int scnt[E_], soff[E_+1], scur[E_];
    int tid = threadIdx.x;
    if (tid < E_) scnt[tid] = 0;
    __syncthreads();
    for (int r = tid; r < TA_; r += 256) atomicAdd(&scnt[g_topk_idx[r]], 1);
    __syncthreads();
    if (tid == 0) {
        soff[0] = 0;
        for (int e = 0; e < E_; e++) soff[e+1] = soff[e] + scnt[e];
    }
    __syncthreads();
    if (tid < E_) {
        scur[tid] = soff[tid];
        g_counts[tid] = scnt[tid];
        g_offsets[tid] = soff[tid];
    }
    if (tid == 0) g_offsets[E_] = TA_;
    __syncthreads();
    for (int r = tid; r < TA_; r += 256) {
        int e = g_topk_idx[r];
        int pos = atomicAdd(&scur[e], 1);
        g_assign_token[pos] = r >> 2;
        g_assign_w[pos]     = g_topk_w[r];
        g_token_pos[r]      = pos;
    }
}

// ---------------- silu(gate)*up --------------------------------------------
__global__ void act_kernel() {
    long long idx = (long long)blockIdx.x*blockDim.x + threadIdx.x;
    if (idx >= (long long)TA_*I_) return;
    int r = (int)(idx / I_), i = (int)(idx % I_);
    float g = g_gu[(long long)r*(2*I_) + i];
    float u = g_gu[(long long)r*(2*I_) + I_ + i];
    g_act[idx] = g/(1.f + __expf(-g))*u;
}

// ---------------- combine 4 expert outputs per token + residual out --------
__global__ void combine_kernel(float* __restrict__ out, int writeRes) {
    int t = blockIdx.x, tid = threadIdx.x;
    int p0 = g_token_pos[t*4+0], p1 = g_token_pos[t*4+1];
    int p2 = g_token_pos[t*4+2], p3 = g_token_pos[t*4+3];
    for (int hh = tid; hh < H_; hh += 256) {
        float v = g_dn[(long long)p0*H_+hh] + g_dn[(long long)p1*H_+hh]
                + g_dn[(long long)p2*H_+hh] + g_dn[(long long)p3*H_+hh];
        out[(long long)t*H_ + hh] = v;
        if (writeRes)
            out[(long long)T_*H_ + (long long)t*H_ + hh] = g_h2[(long long)t*H_ + hh];
    }
}

// ---------------------------------------------------------------------------
extern "C" void kernel_launch(void* const* d_in, const int* in_sizes, int n_in,
                              void* d_out, int out_size) {
    const float* hidden   = (const float*)d_in[1];
    const float* residual = (const float*)d_in[2];
    const float* w_qkv    = (const float*)d_in[3];
    const float* w_o      = (const float*)d_in[4];
    const float* qnw      = (const float*)d_in[5];
    const float* knw      = (const float*)d_in[6];
    const float* inw      = (const float*)d_in[7];
    const float* postw    = (const float*)d_in[8];
    const float* gate_w   = (const float*)d_in[9];
    const float* Wgu      = (const float*)d_in[10];
    const float* Wdn      = (const float*)d_in[11];
    float* out = (float*)d_out;

    float *px, *pres1, *pqkv, *pattn, *pattnproj, *ph2, *px2, *pgu, *pact, *pdn, *passw;
    int *pcnt, *poff, *ptok;
    cudaGetSymbolAddress((void**)&px,        g_x);
    cudaGetSymbolAddress((void**)&pres1,     g_res1);
    cudaGetSymbolAddress((void**)&pqkv,      g_qkv);
    cudaGetSymbolAddress((void**)&pattn,     g_attn);
    cudaGetSymbolAddress((void**)&pattnproj, g_attnproj);
    cudaGetSymbolAddress((void**)&ph2,       g_h2);
    cudaGetSymbolAddress((void**)&px2,       g_x2);
    cudaGetSymbolAddress((void**)&pgu,       g_gu);
    cudaGetSymbolAddress((void**)&pact,      g_act);
    cudaGetSymbolAddress((void**)&pdn,       g_dn);
    cudaGetSymbolAddress((void**)&passw,     g_assign_w);
    cudaGetSymbolAddress((void**)&pcnt,      g_counts);
    cudaGetSymbolAddress((void**)&poff,      g_offsets);
    cudaGetSymbolAddress((void**)&ptok,      g_assign_token);

    // launch order arranged so tgemm(QKV) is launch #4 (the ncu capture slot)
    // h = hidden + residual; res1 = h; x = rmsnorm(h)
    add_norm_kernel<<<T_, 256>>>(hidden, residual, inw, px, pres1);
    rope_cos_kernel<<<(T_*64 + 255)/256, 256>>>();
    rope_sin_kernel<<<(T_*64 + 255)/256, 256>>>();
    // qkv = x @ w_qkv   [1024 x 5120], K=2048
    tgemm<<<dim3(QKVN_/64, T_/128, 1), 256>>>(px, w_qkv, pqkv, T_, QKVN_, H_,
                                              H_, QKVN_, QKVN_,
                                              nullptr, nullptr, nullptr, nullptr, 0);
    // per-head norm + rope
    qknorm_rope_kernel<<<dim3(T_, HQ_+HKV_), 128>>>(qnw, knw);
    // causal GQA attention
    attn_kernel<<<dim3(T_/8, HQ_), 256>>>();
    // attn_out = o @ w_o   [1024 x 2048], K=4096
    tgemm<<<dim3(H_/64, T_/128, 1), 256>>>(pattn, w_o, pattnproj, T_, H_, HQ_*D_,
                                           HQ_*D_, H_, H_,
                                           nullptr, nullptr, nullptr, nullptr, 0);
    // h2 = attn_out + res1; x2 = rmsnorm(h2)
    add_norm_kernel<<<T_, 256>>>(pattnproj, pres1, postw, px2, ph2);
    // router + top-4
    router_kernel<<<T_, 512>>>(gate_w);
    assign_kernel<<<1, 256>>>();
    // per-expert gu = gather(x2) @ W_gu[e]   [cnt x 1536], K=2048
    tgemm<<<dim3(2*I_/64, TA_/128, E_), 256>>>(px2, Wgu, pgu, TA_, 2*I_, H_,
                                               H_, 2*I_, 2*I_,
                                               pcnt, poff, ptok, nullptr,
                                               (long long)H_*2*I_);
    // act = silu(gate)*up
    act_kernel<<<(int)(((long long)TA_*I_ + 255)/256), 256>>>();
    // per-expert down = act @ W_down[e] * routing_w  [cnt x 2048], K=768
    tgemm<<<dim3(H_/64, TA_/128, E_), 256>>>(pact, Wdn, pdn, TA_, H_, I_,
                                             I_, H_, H_,
                                             pcnt, poff, nullptr, passw,
                                             (long long)I_*H_);
    // moe_out + residual out
    combine_kernel<<<T_, 256>>>(out, (out_size >= 2*T_*H_) ? 1 : 0);
}